// round 1
// baseline (speedup 1.0000x reference)
#include <cuda_runtime.h>
#include <cuda_bf16.h>

#define HIDDEN 128
#define MAX_ING 20000
#define MAX_CMP 10000

// Scratch for precomputed per-node partial activations (allocation-free rule:
// __device__ globals). P_ing holds x_ing @ W1[:128] + b1, P_cmp holds x_cmp @ W1[128:].
__device__ float g_P_ing[(size_t)MAX_ING * HIDDEN];
__device__ float g_P_cmp[(size_t)MAX_CMP * HIDDEN];

// ---------------------------------------------------------------------------
// Kernel A: precompute P tables. One block = 32 rows (8 warps x 4 rows/warp).
// W half (128x128 f32 = 64KB) staged in dynamic smem.
// Per k-step per warp: 4 LDS (W) + 4 SHFL (x broadcast) + 16 FFMA -> roughly
// balanced MIO vs FMA.
// ---------------------------------------------------------------------------
extern __shared__ float smemW[];

__global__ void precompute_kernel(const float* __restrict__ xi,
                                  const float* __restrict__ xc,
                                  const float* __restrict__ W1,
                                  const float* __restrict__ b1,
                                  int nIng, int nCmp, int ingBlocks)
{
    const float* X;
    float* P;
    const float* Wsrc;
    int nRows;
    bool ing;
    int bid = blockIdx.x;
    if (bid < ingBlocks) {
        ing = true;  X = xi; P = g_P_ing; Wsrc = W1;                   nRows = nIng;
    } else {
        ing = false; bid -= ingBlocks;
        X = xc; P = g_P_cmp; Wsrc = W1 + HIDDEN * HIDDEN;              nRows = nCmp;
    }

    // Stage this half of W1 ([128][128], row k contiguous in j) into smem.
    for (int i = threadIdx.x; i < HIDDEN * HIDDEN; i += blockDim.x)
        smemW[i] = Wsrc[i];
    __syncthreads();

    const int warp = threadIdx.x >> 5;
    const int lane = threadIdx.x & 31;
    const int r0 = bid * 32 + warp * 4;

    // x for 4 rows, 4 chunks of 32 (x[r][c*32+lane]).
    float xr[4][4];
#pragma unroll
    for (int ri = 0; ri < 4; ri++) {
        int r = r0 + ri;
#pragma unroll
        for (int c = 0; c < 4; c++)
            xr[ri][c] = (r < nRows) ? X[(size_t)r * HIDDEN + c * 32 + lane] : 0.f;
    }

    float acc[4][4];
#pragma unroll
    for (int ri = 0; ri < 4; ri++)
#pragma unroll
        for (int u = 0; u < 4; u++) acc[ri][u] = 0.f;

#pragma unroll
    for (int c = 0; c < 4; c++) {
#pragma unroll 8
        for (int k0 = 0; k0 < 32; k0++) {
            const int k = c * 32 + k0;
            float w[4];
#pragma unroll
            for (int u = 0; u < 4; u++)
                w[u] = smemW[k * HIDDEN + lane + 32 * u];
#pragma unroll
            for (int ri = 0; ri < 4; ri++) {
                float xk = __shfl_sync(0xffffffffu, xr[ri][c], k0);
#pragma unroll
                for (int u = 0; u < 4; u++)
                    acc[ri][u] = fmaf(xk, w[u], acc[ri][u]);
            }
        }
    }

#pragma unroll
    for (int ri = 0; ri < 4; ri++) {
        int r = r0 + ri;
        if (r < nRows) {
#pragma unroll
            for (int u = 0; u < 4; u++) {
                float v = acc[ri][u];
                if (ing) v += b1[lane + 32 * u];   // fold bias into ingredient table only
                P[(size_t)r * HIDDEN + lane + 32 * u] = v;
            }
        }
    }
}

// ---------------------------------------------------------------------------
// Kernel B: per-edge gather + add + relu + dot(W2) + sigmoid.
// One warp per edge; lane l holds channels [4l..4l+3] (float4).
// Indices loaded coalesced 32-at-a-time, distributed by shfl (kills the serial
// idx-load -> row-load dependency for 31 of every 32 edges).
// ---------------------------------------------------------------------------
__global__ void edge_kernel(const int* __restrict__ eidx,
                            const float* __restrict__ W2,
                            const float* __restrict__ b2,
                            float* __restrict__ out,
                            int E, int chunk)
{
    const int gw   = (blockIdx.x * blockDim.x + threadIdx.x) >> 5;
    const int lane = threadIdx.x & 31;

    long e0 = (long)gw * chunk;
    long e1 = e0 + chunk;
    if (e1 > E) e1 = E;
    if (e0 >= e1) return;

    const float4 w2  = reinterpret_cast<const float4*>(W2)[lane];
    const float  b2v = __ldg(b2);

    for (long eb = e0; eb < e1; eb += 32) {
        int myS = 0, myD = 0;
        long ee = eb + lane;
        if (ee < e1) {
            myS = eidx[ee];
            myD = eidx[(long)E + ee];
        }
        const int cnt = (int)((e1 - eb < 32) ? (e1 - eb) : 32);

#pragma unroll 4
        for (int i = 0; i < cnt; i++) {
            int s = __shfl_sync(0xffffffffu, myS, i);
            int d = __shfl_sync(0xffffffffu, myD, i);

            float4 a = reinterpret_cast<const float4*>(g_P_ing + (size_t)s * HIDDEN)[lane];
            float4 c = reinterpret_cast<const float4*>(g_P_cmp + (size_t)d * HIDDEN)[lane];

            float v0 = fmaxf(a.x + c.x, 0.f);
            float v1 = fmaxf(a.y + c.y, 0.f);
            float v2 = fmaxf(a.z + c.z, 0.f);
            float v3 = fmaxf(a.w + c.w, 0.f);

            float t = v0 * w2.x + v1 * w2.y + v2 * w2.z + v3 * w2.w;
#pragma unroll
            for (int off = 16; off > 0; off >>= 1)
                t += __shfl_xor_sync(0xffffffffu, t, off);

            if (lane == 0)
                out[eb + i] = 1.f / (1.f + __expf(-(t + b2v)));
        }
    }
}

// ---------------------------------------------------------------------------
// Launch: precompute -> edge kernel, same stream, graph-capturable.
// ---------------------------------------------------------------------------
extern "C" void kernel_launch(void* const* d_in, const int* in_sizes, int n_in,
                              void* d_out, int out_size)
{
    const float* xi = (const float*)d_in[0];
    const float* xc = (const float*)d_in[1];
    const int*   ei = (const int*)d_in[2];
    const float* W1 = (const float*)d_in[3];
    const float* b1 = (const float*)d_in[4];
    const float* W2 = (const float*)d_in[5];
    const float* b2 = (const float*)d_in[6];
    float* out = (float*)d_out;

    const int nIng = in_sizes[0] / HIDDEN;
    const int nCmp = in_sizes[1] / HIDDEN;
    const int E    = in_sizes[2] / 2;

    const int ingBlocks = (nIng + 31) / 32;
    const int cmpBlocks = (nCmp + 31) / 32;

    const int smemBytes = HIDDEN * HIDDEN * (int)sizeof(float);  // 64 KB
    cudaFuncSetAttribute(precompute_kernel,
                         cudaFuncAttributeMaxDynamicSharedMemorySize, smemBytes);

    precompute_kernel<<<ingBlocks + cmpBlocks, 256, smemBytes>>>(
        xi, xc, W1, b1, nIng, nCmp, ingBlocks);

    const int blocks = 1184;                 // 8 CTAs/SM worth of work
    const int warps  = blocks * (256 / 32);
    const int chunk  = (E + warps - 1) / warps;
    edge_kernel<<<blocks, 256>>>(ei, W2, b2, out, E, chunk);
}